// round 4
// baseline (speedup 1.0000x reference)
#include <cuda_runtime.h>
#include <cuda_bf16.h>
#include <cstdint>

// Problem constants
#define Bsz   64
#define Lsz   64
#define Hsz   128
#define Ssz   64
#define INsz  16
#define TWO_H 256
#define FOUR_H 512

// c history: [s][b][h]
__device__ float g_chist[Ssz * Bsz * Hsz];

// ---------------- helpers ----------------
__device__ __forceinline__ uint32_t smem_u32(const void* p) {
    uint32_t a;
    asm("{ .reg .u64 t; cvta.to.shared.u64 t, %1; cvt.u32.u64 %0, t; }"
        : "=r"(a) : "l"(p));
    return a;
}
__device__ __forceinline__ uint32_t mapa_rank(uint32_t laddr, uint32_t rk) {
    uint32_t ra;
    asm("mapa.shared::cluster.u32 %0, %1, %2;" : "=r"(ra) : "r"(laddr), "r"(rk));
    return ra;
}
__device__ __forceinline__ void st_cluster_f32(uint32_t addr, float v) {
    asm volatile("st.shared::cluster.f32 [%0], %1;" :: "r"(addr), "f"(v) : "memory");
}
__device__ __forceinline__ uint32_t cluster_rank() {
    uint32_t r; asm("mov.u32 %0, %%cluster_ctarank;" : "=r"(r)); return r;
}
__device__ __forceinline__ void cluster_sync() {
    asm volatile("barrier.cluster.arrive.aligned;" ::: "memory");
    asm volatile("barrier.cluster.wait.aligned;" ::: "memory");
}
__device__ __forceinline__ float sigf(float x) {
    return __fdividef(1.0f, 1.0f + __expf(-x));
}
__device__ __forceinline__ float tanh_acc(float x) {
    // tanh(x) = 2*sigmoid(2x) - 1
    return __fmaf_rn(2.0f, sigf(2.0f * x), -1.0f);
}

// ---------------- kernel 1: recurrence ----------------
// Grid: 128 CTAs = 32 clusters x 4 CTAs. Cluster ci owns batches {2ci, 2ci+1}.
// CTA rank r owns h-tile [32r, 32r+32) => W columns {g*128 + 32r + hh : g in 0..3}.
// Smem layout (floats):
//   Wt    [256][128]  k-major slice of W_gates (local col jl = gate*32 + hh_loc)
//   inp   [2][2][256] double-buffered state: (buf, b_local, k)  k<128: c, k>=128: h
//   gpart [8][2][128] per-k-chunk GEMM partials
//   bias  [128]
#define SMEM_FLOATS (32768 + 1024 + 2048 + 128)
#define SMEM_BYTES  (SMEM_FLOATS * 4)

extern "C" __global__ void __cluster_dims__(4, 1, 1) __launch_bounds__(256, 1)
lstm_recur_kernel(const float* __restrict__ emb,
                  const float* __restrict__ Wg,
                  const float* __restrict__ bg)
{
    extern __shared__ float smem[];
    float* Wt     = smem;                 // 32768
    float* inp    = smem + 32768;         // 1024
    float* gpart  = smem + 32768 + 1024;  // 2048
    float* bias_s = smem + 32768 + 1024 + 2048; // 128

    const int tid = threadIdx.x;
    const uint32_t r = cluster_rank();
    const int ci = blockIdx.x >> 2;
    const int b0 = ci * 2;

    // ---- load W slice (k-major) ----
    #pragma unroll 4
    for (int idx = tid; idx < 256 * 128; idx += 256) {
        int k  = idx >> 7;
        int jl = idx & 127;
        int jg = ((jl >> 5) << 7) + (int)(r << 5) + (jl & 31); // gate*128 + r*32 + hh
        Wt[(k << 7) + jl] = Wg[(k << 9) + jg];
    }
    if (tid < 128) {
        int jg = ((tid >> 5) << 7) + (int)(r << 5) + (tid & 31);
        bias_s[tid] = bg[jg];
    }
    // ---- init inp[0] = [embedding[:,0,:], zeros] ----
    for (int idx = tid; idx < 512; idx += 256) {
        int b = idx >> 8, k = idx & 255;
        inp[b * 256 + k] = (k < 128) ? emb[(size_t)(b0 + b) * (Lsz * Hsz) + k] : 0.0f;
    }
    __syncthreads();

    const int j4 = tid & 31;   // j-quad index (GEMM role)
    const int kq = tid >> 5;   // k-chunk 0..7  (GEMM role)
    const int hh = tid & 31;   // update role (tid < 64)
    const int ub = tid >> 5;   // update b     (tid < 64)

    float c_old = 0.0f;        // register-resident c for update threads

    const float4* Wt4 = (const float4*)Wt;
    float4* gp4 = (float4*)gpart;

    for (int t = 0; t < Ssz; ++t) {
        const int cur = t & 1, nxt = cur ^ 1;
        const float* ip = inp + cur * 512;

        // ---- GEMM partials: g_local[jl][b] over k in [32kq, 32kq+32) ----
        float a00 = 0.f, a01 = 0.f, a02 = 0.f, a03 = 0.f;
        float a10 = 0.f, a11 = 0.f, a12 = 0.f, a13 = 0.f;
        #pragma unroll 8
        for (int kk = 0; kk < 32; ++kk) {
            int k = (kq << 5) + kk;
            float4 w = Wt4[(k << 5) + j4];
            float x0 = ip[k];
            float x1 = ip[256 + k];
            a00 = __fmaf_rn(w.x, x0, a00);
            a01 = __fmaf_rn(w.y, x0, a01);
            a02 = __fmaf_rn(w.z, x0, a02);
            a03 = __fmaf_rn(w.w, x0, a03);
            a10 = __fmaf_rn(w.x, x1, a10);
            a11 = __fmaf_rn(w.y, x1, a11);
            a12 = __fmaf_rn(w.z, x1, a12);
            a13 = __fmaf_rn(w.w, x1, a13);
        }
        gp4[(kq * 2 + 0) * 32 + j4] = make_float4(a00, a01, a02, a03);
        gp4[(kq * 2 + 1) * 32 + j4] = make_float4(a10, a11, a12, a13);
        __syncthreads();

        // ---- gate reduce + nonlinearity + state scatter (tid < 64) ----
        if (tid < 64) {
            float f  = bias_s[hh];
            float iv = bias_s[32 + hh];
            float ov = bias_s[64 + hh];
            float cv = bias_s[96 + hh];
            #pragma unroll
            for (int q = 0; q < 8; ++q) {
                const float* gp = gpart + ((q * 2 + ub) << 7);
                f  += gp[hh];
                iv += gp[32 + hh];
                ov += gp[64 + hh];
                cv += gp[96 + hh];
            }
            float cn = sigf(f) * c_old + sigf(iv) * tanh_acc(cv);
            float hn = sigf(ov) * tanh_acc(cn);
            c_old = cn;

            int hglob = (int)(r << 5) + hh;
            g_chist[((t << 6) + (b0 + ub)) * 128 + hglob] = cn;

            uint32_t loc_c = smem_u32(&inp[nxt * 512 + ub * 256 + hglob]);
            uint32_t loc_h = loc_c + 128 * 4;
            #pragma unroll
            for (uint32_t pr = 0; pr < 4; ++pr) {
                st_cluster_f32(mapa_rank(loc_c, pr), cn);
                st_cluster_f32(mapa_rank(loc_h, pr), hn);
            }
        }
        cluster_sync(); // releases remote stores; acquires peers' writes
    }
}

// ---------------- kernel 2: projection + broadcast write ----------------
// Block (b,s): proj[o] = sum_h c_hist[s][b][h]*W_lin[h][o] + b_lin[o];
// write to out rows [s*64, s*64+64) of batch b (identical across l).
extern "C" __global__ void __launch_bounds__(128)
proj_kernel(const float* __restrict__ Wlin,
            const float* __restrict__ blin,
            float* __restrict__ out)
{
    __shared__ float sc[128];
    __shared__ float pred[8][16];
    __shared__ float pv[16];

    const int bs = blockIdx.x;
    const int b = bs >> 6, s = bs & 63;
    const int tid = threadIdx.x;

    sc[tid] = g_chist[((s << 6) + b) * 128 + tid];
    __syncthreads();

    const int o = tid & 15, hq = tid >> 4;   // 8 h-chunks x 16 outputs
    float acc = 0.0f;
    #pragma unroll
    for (int u = 0; u < 16; ++u) {
        int h = (hq << 4) + u;
        acc = __fmaf_rn(sc[h], Wlin[h * 16 + o], acc);
    }
    pred[hq][o] = acc;
    __syncthreads();

    if (tid < 16) {
        float v = blin[tid];
        #pragma unroll
        for (int q = 0; q < 8; ++q) v += pred[q][tid];
        pv[tid] = v;
    }
    __syncthreads();

    // out region base: after trip passthrough (262144 floats)
    float4* dst = (float4*)(out + 262144) + (size_t)((b << 12) + (s << 6)) * 4;
    int c0 = (tid & 3) << 2;
    float4 val = make_float4(pv[c0], pv[c0 + 1], pv[c0 + 2], pv[c0 + 3]);
    dst[tid]       = val;
    dst[tid + 128] = val;  // (tid+128)&3 == tid&3
}

// ---------------- kernel 3: trip passthrough copy ----------------
extern "C" __global__ void __launch_bounds__(256)
trip_copy_kernel(const float4* __restrict__ in, float4* __restrict__ out)
{
    int i = blockIdx.x * 256 + threadIdx.x;   // 65536 float4 = 262144 floats
    out[i] = in[i];
}

// ---------------- launch ----------------
extern "C" void kernel_launch(void* const* d_in, const int* in_sizes, int n_in,
                              void* d_out, int out_size)
{
    const float* trip = (const float*)d_in[0];
    // d_in[1] = valid_len (unused by reference)
    const float* emb  = (const float*)d_in[2];
    const float* Wg   = (const float*)d_in[3];
    const float* bg   = (const float*)d_in[4];
    const float* Wl   = (const float*)d_in[5];
    const float* bl   = (const float*)d_in[6];
    float* out = (float*)d_out;

    cudaFuncSetAttribute(lstm_recur_kernel,
                         cudaFuncAttributeMaxDynamicSharedMemorySize, SMEM_BYTES);

    lstm_recur_kernel<<<128, 256, SMEM_BYTES>>>(emb, Wg, bg);
    proj_kernel<<<Bsz * Ssz, 128>>>(Wl, bl, out);
    trip_copy_kernel<<<256, 256>>>((const float4*)trip, (float4*)out);
}